// round 16
// baseline (speedup 1.0000x reference)
#include <cuda_runtime.h>
#include <cuda_fp16.h>
#include <cstdint>

// Logical GEMM dims in the M4(C) matrix representation:
#define M2 8192    // (b*s)*4 matrix columns c
#define N2 2048    // o*8: (r, pn)
#define K2 2048    // i*8: (q, pk)

// Scratch (__device__ globals; allocation-free rules)
__device__ __align__(256) __half g_A[(size_t)M2 * K2];   // 32 MiB
__device__ __align__(256) __half g_B[(size_t)N2 * K2];   // 8 MiB

static __device__ __forceinline__ uint32_t smem_u32(const void* p) {
    return (uint32_t)__cvta_generic_to_shared(p);
}
static __device__ __forceinline__ void cp_async16(uint32_t s, const void* g) {
    asm volatile("cp.async.cg.shared.global [%0], [%1], 16;\n" :: "r"(s), "l"(g));
}

// ================= compile-time tables (Cl(4,1) ~= M4(C) rep) =================
struct Tables {
    int   xEncA[32][8]; float xEncC[32][8];
    int   wEncA[64][8]; float wEncC[64][8];
    int   decU[32][4];  float decRe[32][4]; float decIm[32][4];
};

constexpr float cfabs(float v) { return v < 0.f ? -v : v; }

constexpr void cmul4c(const float (&Ar)[4][4], const float (&Ai)[4][4],
                      const float (&Br)[4][4], const float (&Bi)[4][4],
                      float (&Cr)[4][4], float (&Ci)[4][4]) {
    for (int i = 0; i < 4; i++)
        for (int j = 0; j < 4; j++) {
            float re = 0.f, im = 0.f;
            for (int k = 0; k < 4; k++) {
                re += Ar[i][k] * Br[k][j] - Ai[i][k] * Bi[k][j];
                im += Ar[i][k] * Bi[k][j] + Ai[i][k] * Br[k][j];
            }
            Cr[i][j] = re; Ci[i][j] = im;
        }
}

constexpr Tables build_tables() {
    Tables T{};
    float Gre[5][4][4] = {}, Gim[5][4][4] = {};
    Gre[0][0][3] = 1; Gre[0][1][2] = 1; Gre[0][2][1] = 1; Gre[0][3][0] = 1;
    Gim[1][0][3] = -1; Gim[1][1][2] = 1; Gim[1][2][1] = -1; Gim[1][3][0] = 1;
    Gre[2][0][2] = 1; Gre[2][1][3] = -1; Gre[2][2][0] = 1; Gre[2][3][1] = -1;
    Gre[3][0][0] = 1; Gre[3][1][1] = 1; Gre[3][2][2] = -1; Gre[3][3][3] = -1;
    { // G5 = i * g1*g2*g3*g4
        float Tr[4][4] = {}, Ti[4][4] = {}, Ur[4][4] = {}, Ui[4][4] = {};
        float Vr[4][4] = {}, Vi[4][4] = {};
        cmul4c(Gre[0], Gim[0], Gre[1], Gim[1], Tr, Ti);
        cmul4c(Tr, Ti, Gre[2], Gim[2], Ur, Ui);
        cmul4c(Ur, Ui, Gre[3], Gim[3], Vr, Vi);
        for (int i = 0; i < 4; i++)
            for (int j = 0; j < 4; j++) { Gre[4][i][j] = -Vi[i][j]; Gim[4][i][j] = Vr[i][j]; }
    }
    float Rre[32][4][4] = {}, Rim[32][4][4] = {};
    for (int a = 0; a < 32; a++) {
        float Rr[4][4] = {}, Ri[4][4] = {};
        Rr[0][0] = Rr[1][1] = Rr[2][2] = Rr[3][3] = 1.f;
        for (int b = 0; b < 5; b++)
            if ((a >> b) & 1) {
                float Tr[4][4] = {}, Ti[4][4] = {};
                cmul4c(Rr, Ri, Gre[b], Gim[b], Tr, Ti);
                for (int i = 0; i < 4; i++)
                    for (int j = 0; j < 4; j++) { Rr[i][j] = Tr[i][j]; Ri[i][j] = Ti[i][j]; }
            }
        for (int i = 0; i < 4; i++)
            for (int j = 0; j < 4; j++) { Rre[a][i][j] = Rr[i][j]; Rim[a][i][j] = Ri[i][j]; }
    }
    for (int u = 0; u < 32; u++) {   // X-encode: u = c*8 + q*2 + pk
        int c = u >> 3, q = (u >> 1) & 3, pk = u & 1, e = 0;
        for (int bl = 0; bl < 32; bl++) {
            float re = Rre[bl][q][c], im = Rim[bl][q][c];
            if (cfabs(re) + cfabs(im) > 0.5f) {
                T.xEncA[u][e] = bl;
                T.xEncC[u][e] = pk ? im : re;
                e++;
            }
        }
    }
    for (int u = 0; u < 64; u++) {   // W-encode: u = (r*2+pn)*8 + q*2 + pk
        int rw = u >> 3, r = rw >> 1, pn = rw & 1;
        int qk = u & 7, q = qk >> 1, pk = qk & 1, e = 0;
        for (int bl = 0; bl < 32; bl++) {
            float re = Rre[bl][r][q], im = Rim[bl][r][q];
            if (cfabs(re) + cfabs(im) > 0.5f) {
                T.wEncA[u][e] = bl;
                T.wEncC[u][e] = (pn == 0) ? (pk == 0 ? re : -im)
                                          : (pk == 0 ? im : re);
                e++;
            }
        }
    }
    for (int bl = 0; bl < 32; bl++)  // decode
        for (int r = 0; r < 4; r++)
            for (int c = 0; c < 4; c++) {
                float re = Rre[bl][r][c], im = Rim[bl][r][c];
                if (cfabs(re) + cfabs(im) > 0.5f) {
                    T.decU[bl][r]  = c * 8 + r * 2;
                    T.decRe[bl][r] = re * 0.25f;
                    T.decIm[bl][r] = im * 0.25f;
                }
            }
    return T;
}

// ---- compile-time unrolled encode terms: coefficients become SASS immediates ----
template<int U, int E>
struct EX {
    static constexpr float C = build_tables().xEncC[U][E];
    static constexpr int   A = build_tables().xEncA[U][E];
    static __device__ __forceinline__ float f(const float (&x)[32]) {
        return C * x[A] + EX<U, E - 1>::f(x);
    }
};
template<int U> struct EX<U, -1> {
    static __device__ __forceinline__ float f(const float (&)[32]) { return 0.f; }
};
template<int C, int Q>
struct FX {
    static __device__ __forceinline__ void f(const float (&x)[32], __half* h) {
        h[Q] = __float2half_rn(EX<C * 8 + Q, 7>::f(x));
        FX<C, Q - 1>::f(x, h);
    }
};
template<int C> struct FX<C, -1> {
    static __device__ __forceinline__ void f(const float (&)[32], __half*) {}
};

template<int U, int E>
struct EW {
    static constexpr float C = build_tables().wEncC[U][E];
    static constexpr int   A = build_tables().wEncA[U][E];
    static __device__ __forceinline__ float f(const float (&x)[32]) {
        return C * x[A] + EW<U, E - 1>::f(x);
    }
};
template<int U> struct EW<U, -1> {
    static __device__ __forceinline__ float f(const float (&)[32]) { return 0.f; }
};
template<int RW, int Q>
struct FW {
    static __device__ __forceinline__ void f(const float (&x)[32], __half* h) {
        h[Q] = __float2half_rn(EW<RW * 8 + Q, 7>::f(x));
        FW<RW, Q - 1>::f(x, h);
    }
};
template<int RW> struct FW<RW, -1> {
    static __device__ __forceinline__ void f(const float (&)[32], __half*) {}
};

// ---- compile-time decode: rep matrices are monomial -> 4 signed adds per blade ----
template<int A, int R>
struct DT {
    static constexpr int   U  = build_tables().decU[A][R];
    static constexpr float CR = build_tables().decRe[A][R] * 4.0f;  // +-1 or 0
    static constexpr float CI = build_tables().decIm[A][R] * 4.0f;  // +-1 or 0
    static __device__ __forceinline__ float f(const float (&V)[32]) {
        float s = DT<A, R - 1>::f(V);
        if constexpr (CR != 0.f) s += CR * V[U];
        if constexpr (CI != 0.f) s += CI * V[U + 1];
        return s;
    }
};
template<int A> struct DT<A, -1> {
    static __device__ __forceinline__ float f(const float (&)[32]) { return 0.f; }
};
template<int A>
struct DAll {
    static __device__ __forceinline__ void f(const float (&V)[32], float (&s)[32]) {
        s[A] = DT<A, 3>::f(V);
        DAll<A - 1>::f(V, s);
    }
};
template<> struct DAll<-1> {
    static __device__ __forceinline__ void f(const float (&)[32], float (&)[32]) {}
};

// ---------------- encode: cp.async warp-local staging, compile-time signs ----------------
// blocks [0,256): w.  blocks [256,2304): x.  Each block: 256 mvs; each warp stages
// its own 32 mvs via cp.async (no block sync, no register round-trip).
// Pitch 36 floats: LDS.128 banks (36i+4q)%32 distinct within each 8-lane phase.
#define EPITCH 36
__global__ void encode_kernel(const float4* __restrict__ x, const float4* __restrict__ w) {
    __shared__ float sx[256 * EPITCH];   // 36 KB
    const int tid = threadIdx.x, lane = tid & 31, warp = tid >> 5;
    const bool isX = (blockIdx.x >= 256);
    const float4* src = isX ? (x + ((size_t)(blockIdx.x - 256) * 256) * 8)
                            : (w + ((size_t)blockIdx.x * 256) * 8);
    // Warp-local stage: 256 consecutive float4 per warp, fully coalesced.
    const float4* srcw = src + (size_t)warp * 256;
    const uint32_t sw = smem_u32(&sx[warp * 32 * EPITCH]);
#pragma unroll
    for (int it = 0; it < 8; it++) {
        int idx = it * 32 + lane;          // 0..255
        int m = idx >> 3, q = idx & 7;
        cp_async16(sw + (m * EPITCH + q * 4) * 4, srcw + idx);
    }
    asm volatile("cp.async.commit_group;\n");
    asm volatile("cp.async.wait_group 0;\n");
    __syncwarp();

    float xr[32];
#pragma unroll
    for (int q = 0; q < 8; q++) {
        float4 v = *reinterpret_cast<const float4*>(&sx[tid * EPITCH + q * 4]);
        xr[4 * q] = v.x; xr[4 * q + 1] = v.y; xr[4 * q + 2] = v.z; xr[4 * q + 3] = v.w;
    }
    if (isX) {
        const size_t mv = (size_t)(blockIdx.x - 256) * 256 + tid;
        const size_t bs = mv >> 8;
        const int ii = (int)(mv & 255);
        __align__(16) __half h0[8], h1[8], h2[8], h3[8];
        FX<0, 7>::f(xr, h0); FX<1, 7>::f(xr, h1);
        FX<2, 7>::f(xr, h2); FX<3, 7>::f(xr, h3);
        *reinterpret_cast<uint4*>(g_A + (bs * 4 + 0) * K2 + ii * 8) = *reinterpret_cast<uint4*>(h0);
        *reinterpret_cast<uint4*>(g_A + (bs * 4 + 1) * K2 + ii * 8) = *reinterpret_cast<uint4*>(h1);
        *reinterpret_cast<uint4*>(g_A + (bs * 4 + 2) * K2 + ii * 8) = *reinterpret_cast<uint4*>(h2);
        *reinterpret_cast<uint4*>(g_A + (bs * 4 + 3) * K2 + ii * 8) = *reinterpret_cast<uint4*>(h3);
    } else {
        const int mv = blockIdx.x * 256 + tid;   // (o,i)
        const int o = mv >> 8, i = mv & 255;
        __align__(16) __half h[8][8];
        FW<0, 7>::f(xr, h[0]); FW<1, 7>::f(xr, h[1]);
        FW<2, 7>::f(xr, h[2]); FW<3, 7>::f(xr, h[3]);
        FW<4, 7>::f(xr, h[4]); FW<5, 7>::f(xr, h[5]);
        FW<6, 7>::f(xr, h[6]); FW<7, 7>::f(xr, h[7]);
#pragma unroll
        for (int rw = 0; rw < 8; rw++)
            *reinterpret_cast<uint4*>(g_B + (size_t)(o * 8 + rw) * K2 + i * 8) =
                *reinterpret_cast<uint4*>(h[rw]);
    }
}

// ---------------- GEMM + fused decode/normalize (R13/R15 mainloop, measured optimum) ----------------
// CTA 128x128, 256 threads (8 warps: 2M x 4N, warp 64x32), 3 stages -> 2 CTAs/SM.
#define BM 128
#define BN 128
#define BK 64
#define STAGES 3
#define NT (K2 / BK)               // 32
#define A_BYTES (BM * 128)         // 16384
#define B_BYTES (BN * 128)         // 16384
#define STAGE_BYTES (A_BYTES + B_BYTES)          // 32768
#define SMEM_BYTES (STAGES * STAGE_BYTES)        // 98304
#define PITCH 136                                // 128 + 8: conflict-free epilogue

__global__ void __launch_bounds__(256, 2) gemm_hmma_kernel(float* __restrict__ out) {
    extern __shared__ char sm[];
    const uint32_t sbase = smem_u32(sm);

    const int tid  = threadIdx.x;
    const int lane = tid & 31;
    const int warp = tid >> 5;
    const int wm = (warp & 1) * 64;      // 2 warps along M
    const int wn = (warp >> 1) * 32;     // 4 warps along N
    const int bm = blockIdx.x * BM;
    const int bn = blockIdx.y * BN;

    const __half* A = g_A;
    const __half* B = g_B;

    float acc[4][4][4];
#pragma unroll
    for (int a = 0; a < 4; a++)
#pragma unroll
        for (int b = 0; b < 4; b++)
#pragma unroll
            for (int c = 0; c < 4; c++) acc[a][b][c] = 0.0f;

    auto load_stage = [&](int t) {
        const uint32_t st = sbase + (t % STAGES) * STAGE_BYTES;
        const int k0 = t * BK;
#pragma unroll
        for (int q = 0; q < 4; q++) {    // A: 1024 chunks / 256 thr
            int c = tid + q * 256;
            int r = c >> 3, cc = c & 7;
            cp_async16(st + r * 128 + ((cc ^ (r & 7)) * 16),
                       A + (size_t)(bm + r) * K2 + k0 + cc * 8);
        }
#pragma unroll
        for (int q = 0; q < 4; q++) {    // B: 1024 chunks
            int c = tid + q * 256;
            int r = c >> 3, cc = c & 7;
            cp_async16(st + A_BYTES + r * 128 + ((cc ^ (r & 7)) * 16),
                       B + (size_t)(bn + r) * K2 + k0 + cc * 8);
        }
        asm volatile("cp.async.commit_group;\n");
    };

    load_stage(0);
    load_stage(1);

    const int aRow = wm + (lane & 15);
    const int aHi  = lane >> 4;
    const int aRx  = aRow & 7;
    const int bRow = wn + (lane & 7) + ((lane & 16) >> 1);
    const int bHi  = (lane >> 3) & 1;
    const int bRx  = bRow & 7;

    for (int t = 0; t < NT; t++) {
        if (t + 1 < NT) asm volatile("cp.async.wait_group 1;\n");
        else            asm volatile("cp.async.wait_group 0;\n");
        __syncthreads();

        if (t + 2 < NT) load_stage(t + 2);

        const uint32_t st = sbase + (t % STAGES) * STAGE_BYTES;
        const uint32_t aB = st + aRow * 128;
        const uint32_t bB = st + A_BYTES + bRow * 128;

#pragma unroll
        for (int ks = 0; ks < 4; ks++) {
            uint32_t a[4][4];
#pragma unroll
            for (int mi = 0; mi < 4; mi++) {
                uint32_t addr = aB + mi * (16 * 128) + (((ks * 2 + aHi) ^ aRx) * 16);
                asm volatile("ldmatrix.sync.aligned.m8n8.x4.shared.b16 {%0,%1,%2,%3}, [%4];\n"
                             : "=r"(a[mi][0]), "=r"(a[mi][1]), "=r"(a[mi][2]), "=r"(a[mi][3])
                             : "r"(addr));
            }
            uint32_t b[4][2];
#pragma unroll
            for (int nb = 0; nb < 2; nb++) {
                uint32_t addr = bB + nb * (16 * 128) + (((ks * 2 + bHi) ^ bRx) * 16);
                asm volatile("ldmatrix.sync.aligned.m8n8.x4.shared.b16 {%0,%1,%2,%3}, [%4];\n"
                             : "=r"(b[2 * nb][0]), "=r"(b[2 * nb][1]),
                               "=r"(b[2 * nb + 1][0]), "=r"(b[2 * nb + 1][1])
                             : "r"(addr));
            }
#pragma unroll
            for (int mi = 0; mi < 4; mi++)
#pragma unroll
                for (int nj = 0; nj < 4; nj++) {
                    asm volatile(
                        "mma.sync.aligned.m16n8k16.row.col.f32.f16.f16.f32 "
                        "{%0,%1,%2,%3},{%4,%5,%6,%7},{%8,%9},{%0,%1,%2,%3};\n"
                        : "+f"(acc[mi][nj][0]), "+f"(acc[mi][nj][1]),
                          "+f"(acc[mi][nj][2]), "+f"(acc[mi][nj][3])
                        : "r"(a[mi][0]), "r"(a[mi][1]), "r"(a[mi][2]), "r"(a[mi][3]),
                          "r"(b[nj][0]), "r"(b[nj][1]));
                }
        }
    }

    // ---------------- epilogue: stage tile in smem ----------------
    __syncthreads();
    float* smf = reinterpret_cast<float*>(sm);
#pragma unroll
    for (int mi = 0; mi < 4; mi++)
#pragma unroll
        for (int h = 0; h < 2; h++) {
            const int row = wm + mi * 16 + h * 8 + (lane >> 2);
            float* p = smf + (size_t)row * PITCH + wn + (lane & 3) * 2;
#pragma unroll
            for (int nj = 0; nj < 4; nj++)
                *reinterpret_cast<float2*>(p + nj * 8) =
                    make_float2(acc[mi][nj][2 * h], acc[mi][nj][2 * h + 1]);
        }
    __syncthreads();

    // -------- thread-per-mv decode + normalize: 512 mvs, no SHFL --------
    const int bs0 = bm >> 2, o0 = bn >> 3;
#pragma unroll 1
    for (int it = 0; it < 2; it++) {
        const int mvloc = warp * 64 + it * 32 + lane;
        const int bsl = mvloc >> 4, ol = mvloc & 15;
        float V[32];
        const float* vp = smf + (size_t)(bsl * 4) * PITCH + ol * 8;
#pragma unroll
        for (int c = 0; c < 4; c++) {
            float4 a0 = *reinterpret_cast<const float4*>(vp + c * PITCH);
            float4 a1 = *reinterpret_cast<const float4*>(vp + c * PITCH + 4);
            V[c * 8 + 0] = a0.x; V[c * 8 + 1] = a0.y;
            V[c * 8 + 2] = a0.z; V[c * 8 + 3] = a0.w;
            V[c * 8 + 4] = a1.x; V[c * 8 + 5] = a1.y;
            V[c * 8 + 6] = a1.z; V[c * 8 + 7] = a1.w;
        }
        float s[32];
        DAll<31>::f(V, s);
        float ss = 1.6e-5f;   // == 1e-6 / 0.25^2 (exact power-of-2 fold of the trace factor)
#pragma unroll
        for (int b = 0; b < 32; b++) ss += s[b] * s[b];
        const float sc = rsqrtf(ss);
        float* op = out + ((size_t)(bs0 + bsl) * 256 + (o0 + ol)) * 32;
#pragma unroll
        for (int q = 0; q < 8; q++)
            *reinterpret_cast<float4*>(op + q * 4) =
                make_float4(s[4 * q] * sc, s[4 * q + 1] * sc,
                            s[4 * q + 2] * sc, s[4 * q + 3] * sc);
    }
}

// ---------------- launch ----------------
extern "C" void kernel_launch(void* const* d_in, const int* in_sizes, int n_in,
                              void* d_out, int out_size) {
    const float* x = (const float*)d_in[0];   // [2,1024,256,32] fp32
    const float* w = (const float*)d_in[1];   // [256,256,32]   fp32
    float* out = (float*)d_out;               // [2,1024,256,32] fp32

    encode_kernel<<<2304, 256>>>((const float4*)x, (const float4*)w);

    cudaFuncSetAttribute(gemm_hmma_kernel,
                         cudaFuncAttributeMaxDynamicSharedMemorySize, SMEM_BYTES);
    dim3 grid(M2 / BM, N2 / BN);   // (64, 16), m-fast
    gemm_hmma_kernel<<<grid, 256, SMEM_BYTES>>>(out);
}

// round 17
// speedup vs baseline: 1.0925x; 1.0925x over previous
#include <cuda_runtime.h>
#include <cuda_fp16.h>
#include <cstdint>

// Logical GEMM dims in the M4(C) matrix representation:
#define M2 8192    // (b*s)*4 matrix columns c
#define N2 2048    // o*8: (r, pn)
#define K2 2048    // i*8: (q, pk)

// Scratch (__device__ globals; allocation-free rules)
__device__ __align__(256) __half g_A[(size_t)M2 * K2];   // 32 MiB
__device__ __align__(256) __half g_B[(size_t)N2 * K2];   // 8 MiB

static __device__ __forceinline__ uint32_t smem_u32(const void* p) {
    return (uint32_t)__cvta_generic_to_shared(p);
}
static __device__ __forceinline__ void cp_async16(uint32_t s, const void* g) {
    asm volatile("cp.async.cg.shared.global [%0], [%1], 16;\n" :: "r"(s), "l"(g));
}

// ================= compile-time tables (Cl(4,1) ~= M4(C) rep) =================
struct Tables {
    int   xEncA[32][8]; float xEncC[32][8];
    int   wEncA[64][8]; float wEncC[64][8];
    int   decU[32][4];  float decRe[32][4]; float decIm[32][4];
};

constexpr float cfabs(float v) { return v < 0.f ? -v : v; }

constexpr void cmul4c(const float (&Ar)[4][4], const float (&Ai)[4][4],
                      const float (&Br)[4][4], const float (&Bi)[4][4],
                      float (&Cr)[4][4], float (&Ci)[4][4]) {
    for (int i = 0; i < 4; i++)
        for (int j = 0; j < 4; j++) {
            float re = 0.f, im = 0.f;
            for (int k = 0; k < 4; k++) {
                re += Ar[i][k] * Br[k][j] - Ai[i][k] * Bi[k][j];
                im += Ar[i][k] * Bi[k][j] + Ai[i][k] * Br[k][j];
            }
            Cr[i][j] = re; Ci[i][j] = im;
        }
}

constexpr Tables build_tables() {
    Tables T{};
    float Gre[5][4][4] = {}, Gim[5][4][4] = {};
    Gre[0][0][3] = 1; Gre[0][1][2] = 1; Gre[0][2][1] = 1; Gre[0][3][0] = 1;
    Gim[1][0][3] = -1; Gim[1][1][2] = 1; Gim[1][2][1] = -1; Gim[1][3][0] = 1;
    Gre[2][0][2] = 1; Gre[2][1][3] = -1; Gre[2][2][0] = 1; Gre[2][3][1] = -1;
    Gre[3][0][0] = 1; Gre[3][1][1] = 1; Gre[3][2][2] = -1; Gre[3][3][3] = -1;
    { // G5 = i * g1*g2*g3*g4
        float Tr[4][4] = {}, Ti[4][4] = {}, Ur[4][4] = {}, Ui[4][4] = {};
        float Vr[4][4] = {}, Vi[4][4] = {};
        cmul4c(Gre[0], Gim[0], Gre[1], Gim[1], Tr, Ti);
        cmul4c(Tr, Ti, Gre[2], Gim[2], Ur, Ui);
        cmul4c(Ur, Ui, Gre[3], Gim[3], Vr, Vi);
        for (int i = 0; i < 4; i++)
            for (int j = 0; j < 4; j++) { Gre[4][i][j] = -Vi[i][j]; Gim[4][i][j] = Vr[i][j]; }
    }
    float Rre[32][4][4] = {}, Rim[32][4][4] = {};
    for (int a = 0; a < 32; a++) {
        float Rr[4][4] = {}, Ri[4][4] = {};
        Rr[0][0] = Rr[1][1] = Rr[2][2] = Rr[3][3] = 1.f;
        for (int b = 0; b < 5; b++)
            if ((a >> b) & 1) {
                float Tr[4][4] = {}, Ti[4][4] = {};
                cmul4c(Rr, Ri, Gre[b], Gim[b], Tr, Ti);
                for (int i = 0; i < 4; i++)
                    for (int j = 0; j < 4; j++) { Rr[i][j] = Tr[i][j]; Ri[i][j] = Ti[i][j]; }
            }
        for (int i = 0; i < 4; i++)
            for (int j = 0; j < 4; j++) { Rre[a][i][j] = Rr[i][j]; Rim[a][i][j] = Ri[i][j]; }
    }
    for (int u = 0; u < 32; u++) {   // X-encode: u = c*8 + q*2 + pk
        int c = u >> 3, q = (u >> 1) & 3, pk = u & 1, e = 0;
        for (int bl = 0; bl < 32; bl++) {
            float re = Rre[bl][q][c], im = Rim[bl][q][c];
            if (cfabs(re) + cfabs(im) > 0.5f) {
                T.xEncA[u][e] = bl;
                T.xEncC[u][e] = pk ? im : re;
                e++;
            }
        }
    }
    for (int u = 0; u < 64; u++) {   // W-encode: u = (r*2+pn)*8 + q*2 + pk
        int rw = u >> 3, r = rw >> 1, pn = rw & 1;
        int qk = u & 7, q = qk >> 1, pk = qk & 1, e = 0;
        for (int bl = 0; bl < 32; bl++) {
            float re = Rre[bl][r][q], im = Rim[bl][r][q];
            if (cfabs(re) + cfabs(im) > 0.5f) {
                T.wEncA[u][e] = bl;
                T.wEncC[u][e] = (pn == 0) ? (pk == 0 ? re : -im)
                                          : (pk == 0 ? im : re);
                e++;
            }
        }
    }
    for (int bl = 0; bl < 32; bl++)  // decode
        for (int r = 0; r < 4; r++)
            for (int c = 0; c < 4; c++) {
                float re = Rre[bl][r][c], im = Rim[bl][r][c];
                if (cfabs(re) + cfabs(im) > 0.5f) {
                    T.decU[bl][r]  = c * 8 + r * 2;
                    T.decRe[bl][r] = re * 0.25f;
                    T.decIm[bl][r] = im * 0.25f;
                }
            }
    return T;
}

// ---- compile-time unrolled encode terms: coefficients become SASS immediates ----
template<int U, int E>
struct EX {
    static constexpr float C = build_tables().xEncC[U][E];
    static constexpr int   A = build_tables().xEncA[U][E];
    static __device__ __forceinline__ float f(const float (&x)[32]) {
        return C * x[A] + EX<U, E - 1>::f(x);
    }
};
template<int U> struct EX<U, -1> {
    static __device__ __forceinline__ float f(const float (&)[32]) { return 0.f; }
};
template<int C, int Q>
struct FX {
    static __device__ __forceinline__ void f(const float (&x)[32], __half* h) {
        h[Q] = __float2half_rn(EX<C * 8 + Q, 7>::f(x));
        FX<C, Q - 1>::f(x, h);
    }
};
template<int C> struct FX<C, -1> {
    static __device__ __forceinline__ void f(const float (&)[32], __half*) {}
};

template<int U, int E>
struct EW {
    static constexpr float C = build_tables().wEncC[U][E];
    static constexpr int   A = build_tables().wEncA[U][E];
    static __device__ __forceinline__ float f(const float (&x)[32]) {
        return C * x[A] + EW<U, E - 1>::f(x);
    }
};
template<int U> struct EW<U, -1> {
    static __device__ __forceinline__ float f(const float (&)[32]) { return 0.f; }
};
template<int RW, int Q>
struct FW {
    static __device__ __forceinline__ void f(const float (&x)[32], __half* h) {
        h[Q] = __float2half_rn(EW<RW * 8 + Q, 7>::f(x));
        FW<RW, Q - 1>::f(x, h);
    }
};
template<int RW> struct FW<RW, -1> {
    static __device__ __forceinline__ void f(const float (&)[32], __half*) {}
};

// ---- compile-time decode: rep matrices are monomial -> 4 signed adds per blade ----
template<int A, int R>
struct DT {
    static constexpr int   U  = build_tables().decU[A][R];
    static constexpr float CR = build_tables().decRe[A][R] * 4.0f;  // +-1 or 0
    static constexpr float CI = build_tables().decIm[A][R] * 4.0f;  // +-1 or 0
    static __device__ __forceinline__ float f(const float (&V)[32]) {
        float s = DT<A, R - 1>::f(V);
        if constexpr (CR != 0.f) s += CR * V[U];
        if constexpr (CI != 0.f) s += CI * V[U + 1];
        return s;
    }
};
template<int A> struct DT<A, -1> {
    static __device__ __forceinline__ float f(const float (&)[32]) { return 0.f; }
};
template<int A>
struct DAll {
    static __device__ __forceinline__ void f(const float (&V)[32], float (&s)[32]) {
        s[A] = DT<A, 3>::f(V);
        DAll<A - 1>::f(V, s);
    }
};
template<> struct DAll<-1> {
    static __device__ __forceinline__ void f(const float (&)[32], float (&)[32]) {}
};

// ---------------- encode (R15 version, measured optimum): smem-staged coalesced loads ----------------
// blocks [0,256): w.  blocks [256,2304): x.  Each block: 256 mvs.
// Staging pitch 36 floats: STS.128 banks (36m+4q)%32 and LDS.128 banks (36i+4q)%32
// are distinct within every 8-lane phase -> conflict-free both directions.
#define EPITCH 36
__global__ void encode_kernel(const float4* __restrict__ x, const float4* __restrict__ w) {
    __shared__ float sx[256 * EPITCH];   // 36 KB
    const int tid = threadIdx.x;
    const bool isX = (blockIdx.x >= 256);
    const float4* src = isX ? (x + ((size_t)(blockIdx.x - 256) * 256) * 8)
                            : (w + ((size_t)blockIdx.x * 256) * 8);
    // Stage: 2048 consecutive float4 loads (fully coalesced)
#pragma unroll
    for (int it = 0; it < 8; it++) {
        int idx = it * 256 + tid;
        float4 v = src[idx];
        int m = idx >> 3, q = idx & 7;
        *reinterpret_cast<float4*>(&sx[m * EPITCH + q * 4]) = v;
    }
    __syncthreads();
    float xr[32];
#pragma unroll
    for (int q = 0; q < 8; q++) {
        float4 v = *reinterpret_cast<const float4*>(&sx[tid * EPITCH + q * 4]);
        xr[4 * q] = v.x; xr[4 * q + 1] = v.y; xr[4 * q + 2] = v.z; xr[4 * q + 3] = v.w;
    }
    if (isX) {
        const size_t mv = (size_t)(blockIdx.x - 256) * 256 + tid;
        const size_t bs = mv >> 8;
        const int ii = (int)(mv & 255);
        __align__(16) __half h0[8], h1[8], h2[8], h3[8];
        FX<0, 7>::f(xr, h0); FX<1, 7>::f(xr, h1);
        FX<2, 7>::f(xr, h2); FX<3, 7>::f(xr, h3);
        *reinterpret_cast<uint4*>(g_A + (bs * 4 + 0) * K2 + ii * 8) = *reinterpret_cast<uint4*>(h0);
        *reinterpret_cast<uint4*>(g_A + (bs * 4 + 1) * K2 + ii * 8) = *reinterpret_cast<uint4*>(h1);
        *reinterpret_cast<uint4*>(g_A + (bs * 4 + 2) * K2 + ii * 8) = *reinterpret_cast<uint4*>(h2);
        *reinterpret_cast<uint4*>(g_A + (bs * 4 + 3) * K2 + ii * 8) = *reinterpret_cast<uint4*>(h3);
    } else {
        const int mv = blockIdx.x * 256 + tid;   // (o,i)
        const int o = mv >> 8, i = mv & 255;
        __align__(16) __half h[8][8];
        FW<0, 7>::f(xr, h[0]); FW<1, 7>::f(xr, h[1]);
        FW<2, 7>::f(xr, h[2]); FW<3, 7>::f(xr, h[3]);
        FW<4, 7>::f(xr, h[4]); FW<5, 7>::f(xr, h[5]);
        FW<6, 7>::f(xr, h[6]); FW<7, 7>::f(xr, h[7]);
#pragma unroll
        for (int rw = 0; rw < 8; rw++)
            *reinterpret_cast<uint4*>(g_B + (size_t)(o * 8 + rw) * K2 + i * 8) =
                *reinterpret_cast<uint4*>(h[rw]);
    }
}

// ---------------- GEMM + fused decode/normalize ----------------
// CTA 128x128, 256 threads (8 warps: 2M x 4N, warp 64x32), 3 stages -> 2 CTAs/SM.
// t-loop unrolled by STAGES: stage offsets are compile-time constants (no per-tile
// IMAD chain between the barrier and the first LDSM).
#define BM 128
#define BN 128
#define BK 64
#define STAGES 3
#define NT (K2 / BK)               // 32 = 3*10 + 2
#define A_BYTES (BM * 128)         // 16384
#define B_BYTES (BN * 128)         // 16384
#define STAGE_BYTES (A_BYTES + B_BYTES)          // 32768
#define SMEM_BYTES (STAGES * STAGE_BYTES)        // 98304
#define PITCH 136                                // 128 + 8: conflict-free epilogue

__global__ void __launch_bounds__(256, 2) gemm_hmma_kernel(float* __restrict__ out) {
    extern __shared__ char sm[];
    const uint32_t sbase = smem_u32(sm);

    const int tid  = threadIdx.x;
    const int lane = tid & 31;
    const int warp = tid >> 5;
    const int wm = (warp & 1) * 64;      // 2 warps along M
    const int wn = (warp >> 1) * 32;     // 4 warps along N
    const int bm = blockIdx.x * BM;
    const int bn = blockIdx.y * BN;

    const __half* A = g_A;
    const __half* B = g_B;

    float acc[4][4][4];
#pragma unroll
    for (int a = 0; a < 4; a++)
#pragma unroll
        for (int b = 0; b < 4; b++)
#pragma unroll
            for (int c = 0; c < 4; c++) acc[a][b][c] = 0.0f;

    // per-thread cp.async source/dest fragments (computed once)
    const int ldr = tid >> 3, ldc = tid & 7;
    const uint32_t ldsw = ((ldc ^ (ldr & 7)) * 16);
    const __half* aSrc = A + (size_t)(bm + ldr) * K2 + ldc * 8;
    const __half* bSrc = B + (size_t)(bn + ldr) * K2 + ldc * 8;

    auto load_stage = [&](int t, uint32_t st) {
        const int k0 = t * BK;
#pragma unroll
        for (int q = 0; q < 4; q++)      // A: 1024 chunks / 256 thr
            cp_async16(st + (ldr + q * 32) * 128 + ldsw,
                       aSrc + (size_t)(q * 32) * K2 + k0);
#pragma unroll
        for (int q = 0; q < 4; q++)      // B: 1024 chunks
            cp_async16(st + A_BYTES + (ldr + q * 32) * 128 + ldsw,
                       bSrc + (size_t)(q * 32) * K2 + k0);
        asm volatile("cp.async.commit_group;\n");
    };

    load_stage(0, sbase);
    load_stage(1, sbase + STAGE_BYTES);

    const int aRow = wm + (lane & 15);
    const int aHi  = lane >> 4;
    const int aRx  = aRow & 7;
    const int bRow = wn + (lane & 7) + ((lane & 16) >> 1);
    const int bHi  = (lane >> 3) & 1;
    const int bRx  = bRow & 7;

    // Per-stage bases, computed once (compile-time stage offsets)
    uint32_t aBs[STAGES], bBs[STAGES];
#pragma unroll
    for (int s = 0; s < STAGES; s++) {
        aBs[s] = sbase + s * STAGE_BYTES + aRow * 128;
        bBs[s] = sbase + s * STAGE_BYTES + A_BYTES + bRow * 128;
    }

    auto tile_math = [&](uint32_t aB, uint32_t bB) {
#pragma unroll
        for (int ks = 0; ks < 4; ks++) {
            uint32_t a[4][4];
#pragma unroll
            for (int mi = 0; mi < 4; mi++) {
                uint32_t addr = aB + mi * (16 * 128) + (((ks * 2 + aHi) ^ aRx) * 16);
                asm volatile("ldmatrix.sync.aligned.m8n8.x4.shared.b16 {%0,%1,%2,%3}, [%4];\n"
                             : "=r"(a[mi][0]), "=r"(a[mi][1]), "=r"(a[mi][2]), "=r"(a[mi][3])
                             : "r"(addr));
            }
            uint32_t b[4][2];
#pragma unroll
            for (int nb = 0; nb < 2; nb++) {
                uint32_t addr = bB + nb * (16 * 128) + (((ks * 2 + bHi) ^ bRx) * 16);
                asm volatile("ldmatrix.sync.aligned.m8n8.x4.shared.b16 {%0,%1,%2,%3}, [%4];\n"
                             : "=r"(b[2 * nb][0]), "=r"(b[2 * nb][1]),
                               "=r"(b[2 * nb + 1][0]), "=r"(b[2 * nb + 1][1])
                             : "r"(addr));
            }
#pragma unroll
            for (int mi = 0; mi < 4; mi++)
#pragma unroll
                for (int nj = 0; nj < 4; nj++) {
                    asm volatile(
                        "mma.sync.aligned.m16n8k16.row.col.f32.f16.f16.f32 "
                        "{%0,%1,%2,%3},{%4,%5,%6,%7},{%8,%9},{%0,%1,%2,%3};\n"
                        : "+f"(acc[mi][nj][0]), "+f"(acc[mi][nj][1]),
                          "+f"(acc[mi][nj][2]), "+f"(acc[mi][nj][3])
                        : "r"(a[mi][0]), "r"(a[mi][1]), "r"(a[mi][2]), "r"(a[mi][3]),
                          "r"(b[nj][0]), "r"(b[nj][1]));
                }
        }
    };

    // 30 tiles in groups of 3 (stage = compile-time), then tail t=30 (s0), t=31 (s1)
    for (int tb = 0; tb < NT - 2; tb += STAGES) {
#pragma unroll
        for (int s = 0; s < STAGES; s++) {
            const int t = tb + s;
            asm volatile("cp.async.wait_group 1;\n");
            __syncthreads();
            if (t + 2 < NT)
                load_stage(t + 2, sbase + ((s + 2) % STAGES) * STAGE_BYTES);
            tile_math(aBs[s], bBs[s]);
        }
    }
    asm volatile("cp.async.wait_group 1;\n");   // t = 30, stage 0
    __syncthreads();
    tile_math(aBs[0], bBs[0]);
    asm volatile("cp.async.wait_group 0;\n");   // t = 31, stage 1
    __syncthreads();
    tile_math(aBs[1], bBs[1]);

    // ---------------- epilogue: stage tile in smem ----------------
    __syncthreads();
    float* smf = reinterpret_cast<float*>(sm);
#pragma unroll
    for (int mi = 0; mi < 4; mi++)
#pragma unroll
        for (int h = 0; h < 2; h++) {
            const int row = wm + mi * 16 + h * 8 + (lane >> 2);
            float* p = smf + (size_t)row * PITCH + wn + (lane & 3) * 2;
#pragma unroll
            for (int nj = 0; nj < 4; nj++)
                *reinterpret_cast<float2*>(p + nj * 8) =
                    make_float2(acc[mi][nj][2 * h], acc[mi][nj][2 * h + 1]);
        }
    __syncthreads();

    // -------- thread-per-mv decode + normalize: 512 mvs, no SHFL --------
    const int bs0 = bm >> 2, o0 = bn >> 3;
#pragma unroll 1
    for (int it = 0; it < 2; it++) {
        const int mvloc = warp * 64 + it * 32 + lane;
        const int bsl = mvloc >> 4, ol = mvloc & 15;
        float V[32];
        const float* vp = smf + (size_t)(bsl * 4) * PITCH + ol * 8;
#pragma unroll
        for (int c = 0; c < 4; c++) {
            float4 a0 = *reinterpret_cast<const float4*>(vp + c * PITCH);
            float4 a1 = *reinterpret_cast<const float4*>(vp + c * PITCH + 4);
            V[c * 8 + 0] = a0.x; V[c * 8 + 1] = a0.y;
            V[c * 8 + 2] = a0.z; V[c * 8 + 3] = a0.w;
            V[c * 8 + 4] = a1.x; V[c * 8 + 5] = a1.y;
            V[c * 8 + 6] = a1.z; V[c * 8 + 7] = a1.w;
        }
        float s[32];
        DAll<31>::f(V, s);
        float ss = 1.6e-5f;   // == 1e-6 / 0.25^2 (exact power-of-2 fold of the trace factor)
#pragma unroll
        for (int b = 0; b < 32; b++) ss += s[b] * s[b];
        const float sc = rsqrtf(ss);
        float* op = out + ((size_t)(bs0 + bsl) * 256 + (o0 + ol)) * 32;
#pragma unroll
        for (int q = 0; q < 8; q++)
            *reinterpret_cast<float4*>(op + q * 4) =
                make_float4(s[4 * q] * sc, s[4 * q + 1] * sc,
                            s[4 * q + 2] * sc, s[4 * q + 3] * sc);
    }
}

// ---------------- launch ----------------
extern "C" void kernel_launch(void* const* d_in, const int* in_sizes, int n_in,
                              void* d_out, int out_size) {
    const float* x = (const float*)d_in[0];   // [2,1024,256,32] fp32
    const float* w = (const float*)d_in[1];   // [256,256,32]   fp32
    float* out = (float*)d_out;               // [2,1024,256,32] fp32

    encode_kernel<<<2304, 256>>>((const float4*)x, (const float4*)w);

    cudaFuncSetAttribute(gemm_hmma_kernel,
                         cudaFuncAttributeMaxDynamicSharedMemorySize, SMEM_BYTES);
    dim3 grid(M2 / BM, N2 / BN);   // (64, 16), m-fast
    gemm_hmma_kernel<<<grid, 256, SMEM_BYTES>>>(out);
}